// round 15
// baseline (speedup 1.0000x reference)
#include <cuda_runtime.h>
#include <cuda_bf16.h>

// ---------------------------------------------------------------------------
// BM25, vocab-collapsed:
//   score = sum_v hq[v] * (hq[v]/(K3+hq[v])) * (K1*hp[v]/(hp[v]+C1)) * idf(DF[v])
//   out   = sigmoid(score)
//
// Single packed count table: query tokens add 1 (low 16 bits), passage tokens
// add 0x10000 (high 16 bits). Counts ~Poisson(8.4) << 65536: no overflow.
//
// Pass B (hist): 16.7M u32 REDs -- LOCKED optimum: 9472x256 grid-stride,
//   no unroll, plain LDG. Binder: LTS atomic pipe @87% busy, ~79.3us
//   (measured twice, bit-stable). Config map in earlier rounds.
// Pass C (score, fused finalize, PDL): launched with programmatic stream
//   serialization -- starts while hist drains, loads DF (hist-independent),
//   then cudaGridDependencySynchronize() before touching the count table.
//   Overlaps the score's DRAM prologue + launch gap with hist's straggler
//   tail. Relaxed RED to g_acc + acq_rel ticket; last block finalizes via
//   atomicExch (read+reset) and writes the sigmoid.
// ---------------------------------------------------------------------------

#define VOCAB_MAX (1 << 20)   // 1,048,576 >= 1,000,000

__device__ unsigned g_h[VOCAB_MAX];    // packed (hp<<16 | hq); zero-init; each
                                       // launch restores zeros => graph-replayable
__device__ float    g_acc;             // score accumulator; reset by last block
__device__ unsigned g_done;            // completion ticket; reset by last block

// ---------------- Pass B: histogram (packed u32 RED, grid-stride) ----------
__global__ __launch_bounds__(256)
void bm25_hist(const int4* __restrict__ ids4, int n4, int half4, unsigned vocab) {
    int stride = gridDim.x * blockDim.x;
    for (int i = blockIdx.x * blockDim.x + threadIdx.x; i < n4; i += stride) {
        int4 t = ids4[i];
        unsigned inc = (i < half4) ? 1u : 0x10000u;  // int4 never straddles rows (L%4==0)
        if ((unsigned)t.x < vocab) atomicAdd(g_h + t.x, inc);
        if ((unsigned)t.y < vocab) atomicAdd(g_h + t.y, inc);
        if ((unsigned)t.z < vocab) atomicAdd(g_h + t.z, inc);
        if ((unsigned)t.w < vocab) atomicAdd(g_h + t.w, inc);
    }
}

// ---------------- Pass C: per-vocab scoring + fused finalize ----------------
__device__ __forceinline__ float bm25_term(unsigned packed, float d, float C1) {
    const float K1 = 1.2f;
    const float K3 = 8.0f;
    float cq = (float)(packed & 0xFFFFu);
    float cp = (float)(packed >> 16);
    // idf = log2((N-d+0.5)/(d+0.5)) ~= LOG2_NP - d*CT - log2(d+0.5)  (d/N<=1.1e-3)
    const float LOG2_NP = 23.0759147f;     // log2(8841823.5)
    const float CT      = 1.631670e-7f;    // 1/((N+0.5)*ln2)
    float idf = (LOG2_NP - d * CT) - __log2f(d + 0.5f);
    float num = cq * cq * (K1 * cp);
    float den = (K3 + cq) * (cp + C1);
    return __fdividef(num, den) * idf;     // exact 0 when cq==0 or cp==0
}

__global__ __launch_bounds__(256)
void bm25_score(const float4* __restrict__ df4, int n4, float C1,
                int tail_base, int tail_n, const float* __restrict__ DF,
                float* __restrict__ out) {
    uint4* h4 = reinterpret_cast<uint4*>(g_h);
    const uint4 z4 = make_uint4(0u, 0u, 0u, 0u);

    int i = blockIdx.x * blockDim.x + threadIdx.x;   // exactly one quad per thread

    // -- hist-independent prologue: DF load overlaps the hist tail (PDL) --
    float4 d = make_float4(0.f, 0.f, 0.f, 0.f);
    if (i < n4) d = df4[i];

    // Wait for the hist grid to complete (implicit trigger => RED visibility).
    cudaGridDependencySynchronize();

    float sum = 0.f;
    if (i < n4) {
        uint4 h = h4[i];
        h4[i] = z4;                         // restore zeros for next replay
        sum += bm25_term(h.x, d.x, C1);
        sum += bm25_term(h.y, d.y, C1);
        sum += bm25_term(h.z, d.z, C1);
        sum += bm25_term(h.w, d.w, C1);
    }

    // warp reduce
    #pragma unroll
    for (int off = 16; off > 0; off >>= 1)
        sum += __shfl_down_sync(0xFFFFFFFFu, sum, off);

    __shared__ float wsum[8];
    int lane = threadIdx.x & 31;
    int wid  = threadIdx.x >> 5;
    if (lane == 0) wsum[wid] = sum;
    __syncthreads();

    if (threadIdx.x == 0) {
        float s = 0.f;
        #pragma unroll
        for (int w = 0; w < 8; w++) s += wsum[w];
        atomicAdd(&g_acc, s);               // relaxed; ordered by the release below

        unsigned ticket;
        asm volatile("atom.acq_rel.gpu.global.add.u32 %0, [%1], %2;"
                     : "=r"(ticket) : "l"(&g_done), "r"(1u) : "memory");
        if (ticket == gridDim.x - 1) {      // last block: finalize
            float sc = atomicExch(&g_acc, 0.f);   // read + reset in one L2 op
            for (int k = 0; k < tail_n; k++) {    // tail_n == 0 for vocab = 1M
                int v = tail_base + k;
                sc += bm25_term(g_h[v], DF[v], C1);
                g_h[v] = 0u;
            }
            out[0] = 1.0f / (1.0f + __expf(-sc));
            g_done = 0u;                    // restore invariant for next replay
        }
    }
}

// ---------------------------------------------------------------------------
extern "C" void kernel_launch(void* const* d_in, const int* in_sizes, int n_in,
                              void* d_out, int out_size) {
    const int*   ids = (const int*)d_in[0];   // [2, L] int32
    // d_in[1] = masks (unused by reference forward)
    const float* DF  = (const float*)d_in[2]; // [vocab] float32

    int twoL  = in_sizes[0];
    int L     = twoL >> 1;
    int vocab = in_sizes[2];

    float Ld = (float)L;
    float C1 = 1.2f * (1.0f - 0.75f + 0.75f * Ld / 56.0f);

    int n4 = vocab >> 2;
    int tail_base = n4 << 2;
    int tail_n = vocab - tail_base;

    // hist: LOCKED peak configuration
    bm25_hist<<<9472, 256>>>((const int4*)ids, twoL >> 2, L >> 2, (unsigned)vocab);

    // score: PDL launch -- overlaps its DF prologue with the hist tail
    cudaLaunchConfig_t cfg = {};
    cfg.gridDim  = dim3((n4 + 255) / 256, 1, 1);
    cfg.blockDim = dim3(256, 1, 1);
    cudaLaunchAttribute attrs[1];
    attrs[0].id = cudaLaunchAttributeProgrammaticStreamSerialization;
    attrs[0].val.programmaticStreamSerializationAllowed = 1;
    cfg.attrs = attrs;
    cfg.numAttrs = 1;
    cudaLaunchKernelEx(&cfg, bm25_score, (const float4*)DF, n4, C1,
                       tail_base, tail_n, DF, (float*)d_out);
}

// round 16
// speedup vs baseline: 1.0404x; 1.0404x over previous
#include <cuda_runtime.h>
#include <cuda_bf16.h>

// ---------------------------------------------------------------------------
// BM25, vocab-collapsed (FINAL — best-measured configuration, 82.4us x2):
//   score = sum_v hq[v] * (hq[v]/(K3+hq[v])) * (K1*hp[v]/(hp[v]+C1)) * idf(DF[v])
//   out   = sigmoid(score)
//
// Single packed count table: query tokens add 1 (low 16 bits), passage tokens
// add 0x10000 (high 16 bits). Counts ~Poisson(8.4) << 65536: no overflow.
//
// Pass B (hist): 16.7M u32 REDs at the LTS-atomic wall (~87% L2 busy,
//   79.3us bit-stable). Locked config: 9472x256 grid-stride, no unroll,
//   plain LDG. Full map: 2368->86.6 | 4736->80.9 | 9472->79.3 (peak) |
//   11840->~79.3 | 16384 no-loop->80.8 (CTA drain) | 18944x128->105.4
//   (L1tex fragmentation) | unroll->-20% | ldcs/f32/split-tables: neutral/worse.
// Pass C (score): one uint4 quad/thread, re-zeroes the table (L2-hot in
//   replay), plain atomicAdd into g_acc (blocks finish async: no contention).
// Pass D (finalize): 1-thread sigmoid + invariant reset.
// Rejected with evidence: fused finalize w/ fence (R2 +19us), acq_rel-ticket
//   fusion (neutral), PDL overlap (R15 +3us: waiting score CTAs steal
//   residency from hist stragglers).
// ---------------------------------------------------------------------------

#define VOCAB_MAX (1 << 20)   // 1,048,576 >= 1,000,000

__device__ unsigned g_h[VOCAB_MAX];    // packed (hp<<16 | hq); zero-init; each
                                       // launch restores zeros => graph-replayable
__device__ float    g_acc;             // score accumulator; reset by finalize

// ---------------- Pass B: histogram (packed u32 RED, grid-stride) ----------
__global__ __launch_bounds__(256)
void bm25_hist(const int4* __restrict__ ids4, int n4, int half4, unsigned vocab) {
    int stride = gridDim.x * blockDim.x;
    for (int i = blockIdx.x * blockDim.x + threadIdx.x; i < n4; i += stride) {
        int4 t = ids4[i];
        unsigned inc = (i < half4) ? 1u : 0x10000u;  // int4 never straddles rows (L%4==0)
        if ((unsigned)t.x < vocab) atomicAdd(g_h + t.x, inc);
        if ((unsigned)t.y < vocab) atomicAdd(g_h + t.y, inc);
        if ((unsigned)t.z < vocab) atomicAdd(g_h + t.z, inc);
        if ((unsigned)t.w < vocab) atomicAdd(g_h + t.w, inc);
    }
}

// ---------------- Pass C: per-vocab scoring ----------------
__device__ __forceinline__ float bm25_term(unsigned packed, float d, float C1) {
    const float K1 = 1.2f;
    const float K3 = 8.0f;
    float cq = (float)(packed & 0xFFFFu);
    float cp = (float)(packed >> 16);
    // idf = log2((N-d+0.5)/(d+0.5)) ~= LOG2_NP - d*CT - log2(d+0.5)  (d/N<=1.1e-3)
    const float LOG2_NP = 23.0759147f;     // log2(8841823.5)
    const float CT      = 1.631670e-7f;    // 1/((N+0.5)*ln2)
    float idf = (LOG2_NP - d * CT) - __log2f(d + 0.5f);
    float num = cq * cq * (K1 * cp);
    float den = (K3 + cq) * (cp + C1);
    return __fdividef(num, den) * idf;     // exact 0 when cq==0 or cp==0
}

__global__ __launch_bounds__(256)
void bm25_score(const float4* __restrict__ df4, int n4, float C1) {
    uint4* h4 = reinterpret_cast<uint4*>(g_h);
    const uint4 z4 = make_uint4(0u, 0u, 0u, 0u);

    float sum = 0.f;
    int i = blockIdx.x * blockDim.x + threadIdx.x;   // exactly one quad per thread
    if (i < n4) {
        uint4  h = h4[i];
        float4 d = df4[i];
        h4[i] = z4;                         // restore zeros for next replay
        sum += bm25_term(h.x, d.x, C1);
        sum += bm25_term(h.y, d.y, C1);
        sum += bm25_term(h.z, d.z, C1);
        sum += bm25_term(h.w, d.w, C1);
    }

    // warp reduce
    #pragma unroll
    for (int off = 16; off > 0; off >>= 1)
        sum += __shfl_down_sync(0xFFFFFFFFu, sum, off);

    __shared__ float wsum[8];
    int lane = threadIdx.x & 31;
    int wid  = threadIdx.x >> 5;
    if (lane == 0) wsum[wid] = sum;
    __syncthreads();
    if (threadIdx.x == 0) {
        float s = 0.f;
        #pragma unroll
        for (int w = 0; w < 8; w++) s += wsum[w];
        atomicAdd(&g_acc, s);               // blocks finish async => no contention
    }
}

// ---------------- Pass D: sigmoid + reset (+ vocab%4 tail) ----------------
__global__ void bm25_finalize(float* __restrict__ out, int tail_base, int tail_n,
                              const float* __restrict__ DF, float C1) {
    float s = g_acc;
    for (int k = 0; k < tail_n; k++) {      // tail_n == 0 for vocab = 1M
        int v = tail_base + k;
        s += bm25_term(g_h[v], DF[v], C1);
        g_h[v] = 0u;
    }
    g_acc = 0.f;                            // restore invariant for next replay
    out[0] = 1.0f / (1.0f + __expf(-s));
}

// ---------------------------------------------------------------------------
extern "C" void kernel_launch(void* const* d_in, const int* in_sizes, int n_in,
                              void* d_out, int out_size) {
    const int*   ids = (const int*)d_in[0];   // [2, L] int32
    // d_in[1] = masks (unused by reference forward)
    const float* DF  = (const float*)d_in[2]; // [vocab] float32

    int twoL  = in_sizes[0];
    int L     = twoL >> 1;
    int vocab = in_sizes[2];

    float Ld = (float)L;
    float C1 = 1.2f * (1.0f - 0.75f + 0.75f * Ld / 56.0f);

    int n4 = vocab >> 2;
    int tail_base = n4 << 2;
    int tail_n = vocab - tail_base;

    // hist: 9472x256 grid-stride -- the measured peak configuration (LOCKED)
    bm25_hist<<<9472, 256>>>((const int4*)ids, twoL >> 2, L >> 2, (unsigned)vocab);
    bm25_score<<<(n4 + 255) / 256, 256>>>((const float4*)DF, n4, C1);
    bm25_finalize<<<1, 1>>>((float*)d_out, tail_base, tail_n, DF, C1);
}